// round 3
// baseline (speedup 1.0000x reference)
#include <cuda_runtime.h>
#include <math.h>

// Problem constants (T=5, B=4, M=4096, C=128, G=1024, H=4, K=16)
#define T_FR   5
#define NPTS   16384
#define CDIM   128
#define GDIM   1024
#define HHEADS 4
#define BATCH  4
#define MP     4096
#define KNB    16

// ---------------- scratch (static __device__ — no allocations) ----------------
__device__ float g_H1[81920 * 128];          // leaky(seq@W1+b1)      ~42 MB
__device__ float g_XLR[5 * 16384 * 512];     // [0..3]=past@Wr, [4]=last@Wl  ~168 MB
__device__ float g_gf[5 * 4 * 1024];         // global_fea means
__device__ float g_attn[16];                 // attn[b][t]
__device__ int   g_nbr[4 * 16384 * 16];      // knn indices (global row ids)
__device__ float g_res[4 * 16384 * 128];     // per-frame GAT outputs ~34 MB

// ---------------- small init ----------------
__global__ void zero_gf_kernel() {
    int i = blockIdx.x * 256 + threadIdx.x;
    if (i < 5 * 4 * 1024) g_gf[i] = 0.f;
}

// ---------------- generic fp32 GEMM, K=128, 64x64 tile, 4x4 micro ----------------
__global__ __launch_bounds__(256) void gemm_k128(
    const float* __restrict__ A, const float* __restrict__ B,
    const float* __restrict__ bias, float* __restrict__ C,
    int Ncols, int leaky)
{
    __shared__ float As[64][68];   // [k][row], padded (68*4B = 272B, 16B-aligned rows)
    __shared__ float Bs[64][68];   // [k][col]
    const int tid = threadIdx.x;
    const int tx = tid & 15, ty = tid >> 4;
    const size_t row0 = (size_t)blockIdx.x * 64;
    const int col0 = blockIdx.y * 64;

    float acc[4][4];
#pragma unroll
    for (int a = 0; a < 4; a++)
#pragma unroll
        for (int bb = 0; bb < 4; bb++) acc[a][bb] = 0.f;

    for (int kc = 0; kc < 2; kc++) {
        const int ks = kc * 64;
#pragma unroll
        for (int it = 0; it < 4; it++) {          // A tile 64 rows x 64 k (transposed store)
            int idx = tid + it * 256;
            int rr = idx >> 4; int kq = (idx & 15) * 4;
            float4 v = *(const float4*)(A + (row0 + rr) * 128 + ks + kq);
            As[kq + 0][rr] = v.x; As[kq + 1][rr] = v.y;
            As[kq + 2][rr] = v.z; As[kq + 3][rr] = v.w;
        }
#pragma unroll
        for (int it = 0; it < 4; it++) {          // B tile 64 k x 64 cols
            int idx = tid + it * 256;
            int kk = idx >> 4; int c4 = (idx & 15) * 4;
            *(float4*)&Bs[kk][c4] = *(const float4*)(B + (size_t)(ks + kk) * Ncols + col0 + c4);
        }
        __syncthreads();
#pragma unroll 16
        for (int k = 0; k < 64; k++) {
            float av[4], bv[4];
#pragma unroll
            for (int j = 0; j < 4; j++) av[j] = As[k][ty + 16 * j];
#pragma unroll
            for (int j = 0; j < 4; j++) bv[j] = Bs[k][tx + 16 * j];
#pragma unroll
            for (int a = 0; a < 4; a++)
#pragma unroll
                for (int bb = 0; bb < 4; bb++) acc[a][bb] += av[a] * bv[bb];
        }
        __syncthreads();
    }
#pragma unroll
    for (int a = 0; a < 4; a++) {
        int r = ty + 16 * a;
#pragma unroll
        for (int bb = 0; bb < 4; bb++) {
            int c = tx + 16 * bb;
            float v = acc[a][bb];
            if (bias) v += bias[col0 + c];
            if (leaky && v < 0.f) v *= 0.2f;
            C[(row0 + r) * Ncols + col0 + c] = v;
        }
    }
}

// ---------------- GEMM2 fused with leaky + column-mean reduce into g_gf ----------------
__global__ __launch_bounds__(256) void gemm2_reduce_kernel(
    const float* __restrict__ A, const float* __restrict__ B,
    const float* __restrict__ bias)
{
    __shared__ float As[64][68];
    __shared__ float Bs[64][68];
    __shared__ float sred[64];
    const int Ncols = GDIM;
    const int tid = threadIdx.x;
    const int tx = tid & 15, ty = tid >> 4;
    const size_t row0 = (size_t)blockIdx.x * 64;
    const int col0 = blockIdx.y * 64;

    float acc[4][4];
#pragma unroll
    for (int a = 0; a < 4; a++)
#pragma unroll
        for (int bb = 0; bb < 4; bb++) acc[a][bb] = 0.f;

    for (int kc = 0; kc < 2; kc++) {
        const int ks = kc * 64;
#pragma unroll
        for (int it = 0; it < 4; it++) {
            int idx = tid + it * 256;
            int rr = idx >> 4; int kq = (idx & 15) * 4;
            float4 v = *(const float4*)(A + (row0 + rr) * 128 + ks + kq);
            As[kq + 0][rr] = v.x; As[kq + 1][rr] = v.y;
            As[kq + 2][rr] = v.z; As[kq + 3][rr] = v.w;
        }
#pragma unroll
        for (int it = 0; it < 4; it++) {
            int idx = tid + it * 256;
            int kk = idx >> 4; int c4 = (idx & 15) * 4;
            *(float4*)&Bs[kk][c4] = *(const float4*)(B + (size_t)(ks + kk) * Ncols + col0 + c4);
        }
        __syncthreads();
#pragma unroll 16
        for (int k = 0; k < 64; k++) {
            float av[4], bv[4];
#pragma unroll
            for (int j = 0; j < 4; j++) av[j] = As[k][ty + 16 * j];
#pragma unroll
            for (int j = 0; j < 4; j++) bv[j] = Bs[k][tx + 16 * j];
#pragma unroll
            for (int a = 0; a < 4; a++)
#pragma unroll
                for (int bb = 0; bb < 4; bb++) acc[a][bb] += av[a] * bv[bb];
        }
        __syncthreads();
    }
    if (tid < 64) sred[tid] = 0.f;
    __syncthreads();
#pragma unroll
    for (int bb = 0; bb < 4; bb++) {
        int c = tx + 16 * bb;
        float bv = bias[col0 + c];
        float s = 0.f;
#pragma unroll
        for (int a = 0; a < 4; a++) {
            float v = acc[a][bb] + bv;
            if (v < 0.f) v *= 0.2f;
            s += v;
        }
        atomicAdd(&sred[c], s);
    }
    __syncthreads();
    if (tid < 64) {
        int t = (int)(row0 >> 14);          // 16384 rows per frame
        int b = (int)((row0 >> 12) & 3);    // 4096 rows per batch
        atomicAdd(&g_gf[(t * 4 + b) * GDIM + col0 + tid], sred[tid] * (1.f / (float)MP));
    }
}

// ---------------- temporal attention weights (tiny) ----------------
__global__ void attn_kernel() {
    __shared__ float sc[16];
    const int tid = threadIdx.x;            // 512
    const int w = tid >> 5, lane = tid & 31;
    const int b = w >> 2, t = w & 3;
    float acc = 0.f;
    for (int g = lane; g < GDIM; g += 32)
        acc += g_gf[(4 * 4 + b) * GDIM + g] * g_gf[(t * 4 + b) * GDIM + g];
#pragma unroll
    for (int o = 16; o; o >>= 1) acc += __shfl_xor_sync(0xffffffffu, acc, o);
    if (lane == 0) sc[b * 4 + t] = acc * (1.f / 32.f);   // /sqrt(1024)
    __syncthreads();
    if (tid < 4) {
        int bb = tid;
        float m = sc[bb * 4];
        for (int i = 1; i < 4; i++) m = fmaxf(m, sc[bb * 4 + i]);
        float e[4], s = 0.f;
        for (int i = 0; i < 4; i++) { e[i] = expf(sc[bb * 4 + i] - m); s += e[i]; }
        for (int i = 0; i < 4; i++) g_attn[bb * 4 + i] = e[i] / s;
    }
}

// ---------------- fused KNN: distance GEMM tile + top-16 selection ----------------
// block = (query-tile of 32, batch, frame). Never materializes D.
#define KNN_SMEM_FLOATS (128*33 + 128*132 + 32*132 + 128 + 32*17 + 32*17)
__global__ __launch_bounds__(256) void knn_kernel(const float* __restrict__ seq) {
    extern __shared__ float sm[];
    float* Ys   = sm;                      // [k][q]  128*33
    float* Xs   = Ys + 128 * 33;           // [k][c]  128*132
    float* Sm   = Xs + 128 * 132;          // [q][c]  32*132
    float* xn   = Sm + 32 * 132;           // 128
    float* topd = xn + 128;                // 32*17 (padded stride 17)
    int*   topi = (int*)(topd + 32 * 17);  // 32*17

    const int tid = threadIdx.x;
    const int qt = blockIdx.x, b = blockIdx.y, fr = blockIdx.z;
    const float* Yb = seq + (size_t)4 * NPTS * CDIM + (size_t)(b * MP + qt * 32) * CDIM;
    const float* Xb = seq + (size_t)fr * NPTS * CDIM + (size_t)b * MP * CDIM;

#pragma unroll
    for (int it = 0; it < 4; it++) {       // Y tile 32 x 128 (transposed)
        int idx = tid + it * 256;
        int q = idx >> 5; int kq = (idx & 31) * 4;
        float4 v = *(const float4*)(Yb + (size_t)q * CDIM + kq);
        Ys[(kq + 0) * 33 + q] = v.x; Ys[(kq + 1) * 33 + q] = v.y;
        Ys[(kq + 2) * 33 + q] = v.z; Ys[(kq + 3) * 33 + q] = v.w;
    }
    for (int e = tid; e < 32 * 16; e += 256) {
        int q = e >> 4, j = e & 15;
        topd[q * 17 + j] = 3.0e38f;
        topi[q * 17 + j] = 0;
    }
    const int tx = tid & 31, ty = tid >> 5;

    for (int cc = 0; cc < MP / 128; cc++) {
        __syncthreads();                   // protect Xs/Sm reuse
#pragma unroll
        for (int it = 0; it < 16; it++) {  // X chunk 128 x 128 (transposed)
            int idx = tid + it * 256;
            int c = idx >> 5; int kq = (idx & 31) * 4;
            float4 v = *(const float4*)(Xb + (size_t)(cc * 128 + c) * CDIM + kq);
            Xs[(kq + 0) * 132 + c] = v.x; Xs[(kq + 1) * 132 + c] = v.y;
            Xs[(kq + 2) * 132 + c] = v.z; Xs[(kq + 3) * 132 + c] = v.w;
        }
        __syncthreads();
        if (tid < 128) {                   // candidate norms
            float s = 0.f;
#pragma unroll 8
            for (int k = 0; k < 128; k++) { float x = Xs[k * 132 + tid]; s += x * x; }
            xn[tid] = s;
        }
        __syncthreads();
        float acc[4][4];
#pragma unroll
        for (int a = 0; a < 4; a++)
#pragma unroll
            for (int bb = 0; bb < 4; bb++) acc[a][bb] = 0.f;
#pragma unroll 8
        for (int k = 0; k < 128; k++) {
            float ya[4], xa[4];
#pragma unroll
            for (int j = 0; j < 4; j++) ya[j] = Ys[k * 33 + ty + 8 * j];
#pragma unroll
            for (int j = 0; j < 4; j++) xa[j] = Xs[k * 132 + tx + 32 * j];
#pragma unroll
            for (int a = 0; a < 4; a++)
#pragma unroll
                for (int bb = 0; bb < 4; bb++) acc[a][bb] += ya[a] * xa[bb];
        }
#pragma unroll
        for (int a = 0; a < 4; a++) {
            int q = ty + 8 * a;
#pragma unroll
            for (int bb = 0; bb < 4; bb++) {
                int c = tx + 32 * bb;
                Sm[q * 132 + c] = xn[c] - 2.f * acc[a][bb];   // |x|^2 - 2 y.x (d minus |y|^2)
            }
        }
        __syncthreads();
        if (tid < 32) {                    // per-query top-16 insertion (tie-stable)
            const int q = tid;
            float* td = topd + q * 17;
            int*   ti = topi + q * 17;
            float worst = td[15];
            for (int c = 0; c < 128; c++) {
                float s = Sm[q * 132 + c];
                if (s < worst) {
                    int j = 15;
                    while (j > 0 && td[j - 1] > s) { td[j] = td[j - 1]; ti[j] = ti[j - 1]; j--; }
                    td[j] = s; ti[j] = cc * 128 + c;
                    worst = td[15];
                }
            }
        }
    }
    __syncthreads();
    for (int e = tid; e < 32 * 16; e += 256) {
        int q = e >> 4, j = e & 15;
        int nglob = b * MP + qt * 32 + q;
        g_nbr[((size_t)fr * NPTS + nglob) * KNB + j] = b * MP + topi[q * 17 + j];
    }
}

// ---------------- GATv2 per (query, frame) ----------------
__global__ __launch_bounds__(128) void gat_kernel(const float* __restrict__ att_w) {
    __shared__ float xls[16 * 512];   // gathered lin_l(last) rows
    __shared__ float xrs[512];
    __shared__ float aws[512];
    __shared__ float es[64];
    __shared__ float as_[64];
    __shared__ int   nb[16];

    const int tid = threadIdx.x;      // 128
    const int n = blockIdx.x, fr = blockIdx.y;
    const float* XL = g_XLR + (size_t)4 * NPTS * 512;
    const float* XR = g_XLR + (size_t)fr * NPTS * 512;

    *(float4*)&xrs[tid * 4] = *(const float4*)(XR + (size_t)n * 512 + tid * 4);
    *(float4*)&aws[tid * 4] = *(const float4*)(att_w + tid * 4);
    if (tid < 16) nb[tid] = g_nbr[((size_t)fr * NPTS + n) * KNB + tid];
    __syncthreads();
#pragma unroll
    for (int k = 0; k < 16; k++)
        *(float4*)&xls[k * 512 + tid * 4] = *(const float4*)(XL + (size_t)nb[k] * 512 + tid * 4);
    __syncthreads();

    if (tid < 64) {                   // e[k][h] = att_w[h] . leaky(xlj + xr)
        const int k = tid & 15, h = tid >> 4;
        float acc = 0.f;
#pragma unroll 4
        for (int cc = 0; cc < 128; cc++) {
            int c = (tid + cc) & 127; // stagger -> conflict-free
            float v = xls[k * 512 + h * 128 + c] + xrs[h * 128 + c];
            v = (v < 0.f) ? 0.2f * v : v;
            acc += aws[h * 128 + c] * v;
        }
        es[h * 16 + k] = acc;
    }
    __syncthreads();
    if (tid < 4) {                    // softmax over k per head
        const int h = tid;
        float m = -1e30f;
        for (int k = 0; k < 16; k++) m = fmaxf(m, es[h * 16 + k]);
        float ex[16], s = 0.f;
        for (int k = 0; k < 16; k++) { ex[k] = expf(es[h * 16 + k] - m); s += ex[k]; }
        float inv = 1.f / s;
        for (int k = 0; k < 16; k++) as_[h * 16 + k] = ex[k] * inv;
    }
    __syncthreads();
    {
        float o = 0.f;
#pragma unroll
        for (int h = 0; h < 4; h++) {
            float oh = 0.f;
#pragma unroll
            for (int k = 0; k < 16; k++)
                oh += as_[h * 16 + k] * xls[k * 512 + h * 128 + tid];
            o += oh;
        }
        g_res[((size_t)fr * NPTS + n) * CDIM + tid] = o * 0.25f;  // mean over heads
    }
}

// ---------------- final: weighted sum over frames + concat ----------------
__global__ __launch_bounds__(128) void final_kernel(const float* __restrict__ seq,
                                                    float* __restrict__ out) {
    const int n = blockIdx.x, c = threadIdx.x;
    const int b = n >> 12;
    float w = 0.f;
#pragma unroll
    for (int i = 0; i < 4; i++)
        w += g_attn[b * 4 + i] * g_res[((size_t)i * NPTS + n) * CDIM + c];
    const float* last = seq + (size_t)4 * NPTS * CDIM;
    out[(size_t)n * 256 + c]       = last[(size_t)n * CDIM + c];
    out[(size_t)n * 256 + 128 + c] = w;
}

// ---------------- launch ----------------
extern "C" void kernel_launch(void* const* d_in, const int* in_sizes, int n_in,
                              void* d_out, int out_size) {
    (void)in_sizes; (void)n_in; (void)out_size;
    const float* seq  = (const float*)d_in[0];
    const float* W1   = (const float*)d_in[1];
    const float* b1   = (const float*)d_in[2];
    const float* W2   = (const float*)d_in[3];
    const float* b2   = (const float*)d_in[4];
    const float* Wl   = (const float*)d_in[5];
    const float* Wr   = (const float*)d_in[6];
    const float* attw = (const float*)d_in[7];
    float* out = (float*)d_out;

    float *pH1, *pXLR;
    cudaGetSymbolAddress((void**)&pH1, g_H1);
    cudaGetSymbolAddress((void**)&pXLR, g_XLR);

    zero_gf_kernel<<<80, 256>>>();

    // H1 = leaky(seq @ W1 + b1)   [81920 x 128]
    gemm_k128<<<dim3(81920 / 64, 128 / 64), 256>>>(seq, W1, b1, pH1, 128, 1);

    // global_fea = mean_m leaky(H1 @ W2 + b2)
    gemm2_reduce_kernel<<<dim3(81920 / 64, GDIM / 64), 256>>>(pH1, W2, b2);

    attn_kernel<<<1, 512>>>();

    // XLR[z] = (z<4 ? past_z @ Wr : last @ Wl)   [16384 x 512] each
    for (int z = 0; z < 5; z++)
        gemm_k128<<<dim3(NPTS / 64, 512 / 64), 256>>>(
            seq + (size_t)z * NPTS * CDIM, (z == 4) ? Wl : Wr, nullptr,
            pXLR + (size_t)z * NPTS * 512, 512, 0);

    // KNN per (frame, batch): fused distance GEMM + top-16
    const int knn_smem = KNN_SMEM_FLOATS * 4;
    cudaFuncSetAttribute(knn_kernel, cudaFuncAttributeMaxDynamicSharedMemorySize, knn_smem);
    knn_kernel<<<dim3(MP / 32, BATCH, 4), 256, knn_smem>>>(seq);

    // GATv2 per (query, frame)
    gat_kernel<<<dim3(NPTS, 4), 128>>>(attw);

    final_kernel<<<NPTS, 128>>>(seq, out);
}

// round 5
// speedup vs baseline: 2.3837x; 2.3837x over previous
#include <cuda_runtime.h>
#include <cuda_bf16.h>
#include <cstdint>

#define NPTS 16384
#define MP   4096
#define KNB  16

// ---------------- helpers ----------------
__device__ __forceinline__ uint32_t s2u(const void* p) {
    uint32_t a;
    asm("{ .reg .u64 t; cvta.to.shared.u64 t, %1; cvt.u32.u64 %0, t; }" : "=r"(a) : "l"(p));
    return a;
}
// [128][128] bf16 tile, 256B rows, 16B chunks XOR-swizzled by row
__device__ __forceinline__ uint32_t tile_off(int r, int c16) {
    return (uint32_t)(r * 256 + ((c16 ^ (r & 7)) << 4));
}
__device__ __forceinline__ void fill_tile(char* dst, const __nv_bfloat16* __restrict__ src, int tid) {
#pragma unroll
    for (int it = 0; it < 8; it++) {
        int idx = tid + it * 256;
        int r = idx >> 4, c16 = idx & 15;
        *(uint4*)(dst + tile_off(r, c16)) = *(const uint4*)(src + r * 128 + c16 * 8);
    }
}
__device__ __forceinline__ void ldmA(uint32_t* a, uint32_t base, int mrow, int kcol, int lane) {
    uint32_t addr = base + tile_off(mrow + (lane & 15), (kcol >> 3) + (lane >> 4));
    asm volatile("ldmatrix.sync.aligned.m8n8.x4.shared.b16 {%0,%1,%2,%3}, [%4];"
        : "=r"(a[0]), "=r"(a[1]), "=r"(a[2]), "=r"(a[3]) : "r"(addr));
}
__device__ __forceinline__ void ldmB(uint32_t* b, uint32_t base, int ncol, int kcol, int lane) {
    uint32_t addr = base + tile_off(ncol + (lane & 7), (kcol >> 3) + ((lane >> 3) & 1));
    asm volatile("ldmatrix.sync.aligned.m8n8.x2.shared.b16 {%0,%1}, [%2];"
        : "=r"(b[0]), "=r"(b[1]) : "r"(addr));
}
__device__ __forceinline__ void mma16816(float* d, const uint32_t* a, const uint32_t* b) {
    asm volatile("mma.sync.aligned.m16n8k16.row.col.f32.bf16.bf16.f32 "
        "{%0,%1,%2,%3}, {%4,%5,%6,%7}, {%8,%9}, {%0,%1,%2,%3};"
        : "+f"(d[0]), "+f"(d[1]), "+f"(d[2]), "+f"(d[3])
        : "r"(a[0]), "r"(a[1]), "r"(a[2]), "r"(a[3]), "r"(b[0]), "r"(b[1]));
}
__device__ __forceinline__ float leaky_f(float v) { return v < 0.f ? 0.2f * v : v; }

// split-bf16 3-product 128x128x128 tile: warp (wm,wn) owns 64x32
__device__ __forceinline__ void mma_core(uint32_t sA, uint32_t sB, int wm, int wn, int lane,
                                         float acc[4][4][4]) {
#pragma unroll 1
    for (int ks = 0; ks < 8; ks++) {
        const int kc = ks * 16;
        uint32_t ah[4][4], al[4][4], bh[4][2], bl[4][2];
#pragma unroll
        for (int mi = 0; mi < 4; mi++) {
            ldmA(ah[mi], sA, wm * 64 + mi * 16, kc, lane);
            ldmA(al[mi], sA + 32768, wm * 64 + mi * 16, kc, lane);
        }
#pragma unroll
        for (int ni = 0; ni < 4; ni++) {
            ldmB(bh[ni], sB, wn * 32 + ni * 8, kc, lane);
            ldmB(bl[ni], sB + 32768, wn * 32 + ni * 8, kc, lane);
        }
#pragma unroll
        for (int mi = 0; mi < 4; mi++)
#pragma unroll
            for (int ni = 0; ni < 4; ni++) {
                mma16816(acc[mi][ni], ah[mi], bh[ni]);
                mma16816(acc[mi][ni], ah[mi], bl[ni]);
                mma16816(acc[mi][ni], al[mi], bh[ni]);
            }
    }
}
__device__ __forceinline__ void stage_acc(float* Sm, int wm, int wn, int lane, float acc[4][4][4]) {
#pragma unroll
    for (int mi = 0; mi < 4; mi++)
#pragma unroll
        for (int ni = 0; ni < 4; ni++) {
            int r = wm * 64 + mi * 16 + (lane >> 2);
            int c = wn * 32 + ni * 8 + (lane & 3) * 2;
            Sm[r * 132 + c]       = acc[mi][ni][0];
            Sm[r * 132 + c + 1]   = acc[mi][ni][1];
            Sm[(r + 8) * 132 + c]     = acc[mi][ni][2];
            Sm[(r + 8) * 132 + c + 1] = acc[mi][ni][3];
        }
}

// ---------------- scratch ----------------
__device__ __nv_bfloat16 g_sh[81920 * 128], g_sl[81920 * 128];
__device__ __nv_bfloat16 g_H1h[81920 * 128], g_H1l[81920 * 128];
__device__ __nv_bfloat16 g_w1h[128 * 128],  g_w1l[128 * 128];
__device__ __nv_bfloat16 g_w2h[1024 * 128], g_w2l[1024 * 128];
__device__ __nv_bfloat16 g_wlh[512 * 128],  g_wll[512 * 128];
__device__ __nv_bfloat16 g_wrh[512 * 128],  g_wrl[512 * 128];
__device__ float g_xn[65536];
__device__ float g_XLR[5 * 16384 * 512];
__device__ float g_gf[5 * 4 * 1024];
__device__ float g_attn[16];
__device__ int   g_nbr[4 * 16384 * 16];
__device__ float g_res[4 * 16384 * 128];

// ---------------- preludes ----------------
__global__ void zero_gf_kernel() {
    int i = blockIdx.x * 256 + threadIdx.x;
    if (i < 5 * 4 * 1024) g_gf[i] = 0.f;
}
__global__ void split_seq_kernel(const float* __restrict__ seq) {
    size_t i = (size_t)blockIdx.x * 256 + threadIdx.x;
    float4 v = ((const float4*)seq)[i];
    float x[4] = {v.x, v.y, v.z, v.w};
    unsigned short h[4], l[4];
#pragma unroll
    for (int j = 0; j < 4; j++) {
        __nv_bfloat16 hb = __float2bfloat16(x[j]);
        h[j] = __bfloat16_as_ushort(hb);
        l[j] = __bfloat16_as_ushort(__float2bfloat16(x[j] - __bfloat162float(hb)));
    }
    uint2 H, L;
    H.x = ((uint32_t)h[1] << 16) | h[0]; H.y = ((uint32_t)h[3] << 16) | h[2];
    L.x = ((uint32_t)l[1] << 16) | l[0]; L.y = ((uint32_t)l[3] << 16) | l[2];
    ((uint2*)g_sh)[i] = H; ((uint2*)g_sl)[i] = L;
}
__global__ void norm_kernel(const float* __restrict__ seq) {
    int r = blockIdx.x * 128 + threadIdx.x;
    const float4* p = (const float4*)(seq + (size_t)r * 128);
    float s = 0.f;
#pragma unroll 8
    for (int i = 0; i < 32; i++) { float4 v = p[i]; s += v.x*v.x + v.y*v.y + v.z*v.z + v.w*v.w; }
    g_xn[r] = s;
}
// W[128][N] -> dst[N][128] hi/lo
__global__ void tsplit_kernel(const float* __restrict__ src, __nv_bfloat16* __restrict__ dh,
                              __nv_bfloat16* __restrict__ dl, int N) {
    __shared__ float t[32][33];
    int n0 = blockIdx.x * 32, k0 = blockIdx.y * 32;
    int tx = threadIdx.x, ty = threadIdx.y;
#pragma unroll
    for (int j = 0; j < 4; j++) t[ty + 8 * j][tx] = src[(size_t)(k0 + ty + 8 * j) * N + n0 + tx];
    __syncthreads();
#pragma unroll
    for (int j = 0; j < 4; j++) {
        int n = n0 + ty + 8 * j, k = k0 + tx;
        float v = t[tx][ty + 8 * j];
        __nv_bfloat16 hb = __float2bfloat16(v);
        dh[(size_t)n * 128 + k] = hb;
        dl[(size_t)n * 128 + k] = __float2bfloat16(v - __bfloat162float(hb));
    }
}

// ---------------- generic MMA GEMM: mode 0=H1, 1=gf(colblk), 2=XLR ----------------
// smem: A hi@0 lo@32768, B hi@65536 lo@98304; staging f32[128][132] overlaps [0,67584); bias@131072
#define GSMEM (131072 + 512)
__global__ __launch_bounds__(256, 1) void mma_gemm_kernel(int mode, const float* __restrict__ bias) {
    extern __shared__ char sm[];
    const uint32_t sA = s2u(sm), sB = sA + 65536;
    float* Sm = (float*)sm;
    float* sbias = (float*)(sm + 131072);
    const int tid = threadIdx.x, lane = tid & 31, wid = tid >> 5;
    const int wm = wid & 1, wn = wid >> 1;
    const size_t row0 = (size_t)blockIdx.x * 128;
    const int yb = blockIdx.y;

    const __nv_bfloat16 *Ah, *Al, *Bh, *Bl;
    if (mode == 0)      { Ah = g_sh + row0 * 128;  Al = g_sl + row0 * 128;  Bh = g_w1h; Bl = g_w1l; }
    else if (mode == 1) { Ah = g_H1h + row0 * 128; Al = g_H1l + row0 * 128;
                          Bh = g_w2h + yb * 16384; Bl = g_w2l + yb * 16384; }
    else { int z = yb >> 2, nb = yb & 3;
           Ah = g_sh + ((size_t)z * NPTS + row0) * 128; Al = g_sl + ((size_t)z * NPTS + row0) * 128;
           Bh = ((z == 4) ? g_wlh : g_wrh) + nb * 16384;
           Bl = ((z == 4) ? g_wll : g_wrl) + nb * 16384; }

    fill_tile(sm, Ah, tid);
    fill_tile(sm + 32768, Al, tid);
    fill_tile(sm + 65536, Bh, tid);
    fill_tile(sm + 98304, Bl, tid);
    if (mode == 0 && tid < 128) sbias[tid] = bias[tid];
    if (mode == 1 && tid < 128) sbias[tid] = bias[yb * 128 + tid];
    __syncthreads();

    float acc[4][4][4];
#pragma unroll
    for (int mi = 0; mi < 4; mi++)
#pragma unroll
        for (int ni = 0; ni < 4; ni++)
#pragma unroll
            for (int j = 0; j < 4; j++) acc[mi][ni][j] = 0.f;

    mma_core(sA, sB, wm, wn, lane, acc);
    __syncthreads();                      // all ldmatrix done before staging overwrites A/B
    stage_acc(Sm, wm, wn, lane, acc);
    __syncthreads();

    if (mode == 0) {
        for (int idx = tid; idx < 8192; idx += 256) {
            int r = idx >> 6, cp = idx & 63, c = cp * 2;
            float v0 = leaky_f(Sm[r * 132 + c]     + sbias[c]);
            float v1 = leaky_f(Sm[r * 132 + c + 1] + sbias[c + 1]);
            __nv_bfloat16 h0 = __float2bfloat16(v0), h1 = __float2bfloat16(v1);
            __nv_bfloat16 l0 = __float2bfloat16(v0 - __bfloat162float(h0));
            __nv_bfloat16 l1 = __float2bfloat16(v1 - __bfloat162float(h1));
            ((uint32_t*)g_H1h)[(row0 + r) * 64 + cp] =
                ((uint32_t)__bfloat16_as_ushort(h1) << 16) | __bfloat16_as_ushort(h0);
            ((uint32_t*)g_H1l)[(row0 + r) * 64 + cp] =
                ((uint32_t)__bfloat16_as_ushort(l1) << 16) | __bfloat16_as_ushort(l0);
        }
    } else if (mode == 1) {
        int c = tid & 127, half = tid >> 7;
        float s = 0.f;
        for (int r = half * 64; r < half * 64 + 64; r++)
            s += leaky_f(Sm[r * 132 + c] + sbias[c]);
        int t = (int)(row0 >> 14), b = (int)((row0 >> 12) & 3);
        atomicAdd(&g_gf[(t * 4 + b) * 1024 + yb * 128 + c], s * (1.f / 4096.f));
    } else {
        int z = yb >> 2, nb = yb & 3;
        float* dst = g_XLR + ((size_t)z * NPTS + row0) * 512 + nb * 128;
        for (int r = wid; r < 128; r += 8)
            *(float4*)(dst + (size_t)r * 512 + lane * 4) = *(float4*)&Sm[r * 132 + lane * 4];
    }
}

// ---------------- KNN: distance MMA + fused top-16 ----------------
// smem: A@0(64K) B@65536(64K) Sm@131072(67584) xn@198656(512) topd@199168(8704) topi@207872(8704)
#define KSMEM 216576
__global__ __launch_bounds__(256, 1) void knn_kernel() {
    extern __shared__ char sm[];
    const uint32_t sA = s2u(sm), sB = sA + 65536;
    float* Sm  = (float*)(sm + 131072);
    float* xnS = (float*)(sm + 198656);
    const int tid = threadIdx.x, lane = tid & 31, wid = tid >> 5;
    const int wm = wid & 1, wn = wid >> 1;
    const int qt = blockIdx.x, b = blockIdx.y, fr = blockIdx.z;
    float* td = (float*)(sm + 199168) + (tid & 127) * 17;
    int*   ti = (int*)(sm + 207872)   + (tid & 127) * 17;

    const size_t yoff = ((size_t)4 * NPTS + b * MP + qt * 128) * 128;
    fill_tile(sm, g_sh + yoff, tid);
    fill_tile(sm + 32768, g_sl + yoff, tid);
    if (tid < 128) {
#pragma unroll
        for (int j = 0; j < 16; j++) { td[j] = 3.0e38f; ti[j] = 0; }
    }
    float worst = 3.0e38f;

    for (int cc = 0; cc < 32; cc++) {
        const size_t xoff = ((size_t)fr * NPTS + b * MP + cc * 128) * 128;
        fill_tile(sm + 65536, g_sh + xoff, tid);
        fill_tile(sm + 98304, g_sl + xoff, tid);
        if (tid < 128) xnS[tid] = g_xn[fr * NPTS + b * MP + cc * 128 + tid];
        __syncthreads();

        float acc[4][4][4];
#pragma unroll
        for (int mi = 0; mi < 4; mi++)
#pragma unroll
            for (int ni = 0; ni < 4; ni++)
#pragma unroll
                for (int j = 0; j < 4; j++) acc[mi][ni][j] = 0.f;
        mma_core(sA, sB, wm, wn, lane, acc);
        stage_acc(Sm, wm, wn, lane, acc);
        __syncthreads();

        if (tid < 128) {                  // tie-stable top-16, index order
            const int q = tid;
            for (int c = 0; c < 128; c++) {
                float s = xnS[c] - 2.f * Sm[q * 132 + c];
                if (s < worst) {
                    int p = 15;
                    while (p > 0 && td[p - 1] > s) { td[p] = td[p - 1]; ti[p] = ti[p - 1]; p--; }
                    td[p] = s; ti[p] = cc * 128 + c;
                    worst = td[15];
                }
            }
        }
        __syncthreads();
    }
    if (tid < 128) {
        const size_t nrow = ((size_t)fr * NPTS + b * MP + qt * 128 + tid) * KNB;
#pragma unroll
        for (int j = 0; j < 16; j++) g_nbr[nrow + j] = b * MP + ti[j];
    }
}

// ---------------- attn / gat / final (validated in R1) ----------------
__global__ void attn_kernel() {
    __shared__ float sc[16];
    const int tid = threadIdx.x, w = tid >> 5, lane = tid & 31;
    const int b = w >> 2, t = w & 3;
    float acc = 0.f;
    for (int g = lane; g < 1024; g += 32)
        acc += g_gf[(16 + b) * 1024 + g] * g_gf[(t * 4 + b) * 1024 + g];
#pragma unroll
    for (int o = 16; o; o >>= 1) acc += __shfl_xor_sync(0xffffffffu, acc, o);
    if (lane == 0) sc[b * 4 + t] = acc * (1.f / 32.f);
    __syncthreads();
    if (tid < 4) {
        int bb = tid;
        float m = sc[bb * 4];
        for (int i = 1; i < 4; i++) m = fmaxf(m, sc[bb * 4 + i]);
        float e[4], s = 0.f;
        for (int i = 0; i < 4; i++) { e[i] = expf(sc[bb * 4 + i] - m); s += e[i]; }
        for (int i = 0; i < 4; i++) g_attn[bb * 4 + i] = e[i] / s;
    }
}
__global__ __launch_bounds__(128) void gat_kernel(const float* __restrict__ att_w) {
    __shared__ float xls[16 * 512], xrs[512], aws[512], es[64], as_[64];
    __shared__ int nb[16];
    const int tid = threadIdx.x, n = blockIdx.x, fr = blockIdx.y;
    const float* XL = g_XLR + (size_t)4 * NPTS * 512;
    const float* XR = g_XLR + (size_t)fr * NPTS * 512;
    *(float4*)&xrs[tid * 4] = *(const float4*)(XR + (size_t)n * 512 + tid * 4);
    *(float4*)&aws[tid * 4] = *(const float4*)(att_w + tid * 4);
    if (tid < 16) nb[tid] = g_nbr[((size_t)fr * NPTS + n) * KNB + tid];
    __syncthreads();
#pragma unroll
    for (int k = 0; k < 16; k++)
        *(float4*)&xls[k * 512 + tid * 4] = *(const float4*)(XL + (size_t)nb[k] * 512 + tid * 4);
    __syncthreads();
    if (tid < 64) {
        const int k = tid & 15, h = tid >> 4;
        float acc = 0.f;
#pragma unroll 4
        for (int cc = 0; cc < 128; cc++) {
            int c = (tid + cc) & 127;
            float v = xls[k * 512 + h * 128 + c] + xrs[h * 128 + c];
            acc += aws[h * 128 + c] * (v < 0.f ? 0.2f * v : v);
        }
        es[h * 16 + k] = acc;
    }
    __syncthreads();
    if (tid < 4) {
        const int h = tid;
        float m = -1e30f;
        for (int k = 0; k < 16; k++) m = fmaxf(m, es[h * 16 + k]);
        float ex[16], s = 0.f;
        for (int k = 0; k < 16; k++) { ex[k] = expf(es[h * 16 + k] - m); s += ex[k]; }
        for (int k = 0; k < 16; k++) as_[h * 16 + k] = ex[k] / s;
    }
    __syncthreads();
    float o = 0.f;
#pragma unroll
    for (int h = 0; h < 4; h++) {
        float oh = 0.f;
#pragma unroll
        for (int k = 0; k < 16; k++) oh += as_[h * 16 + k] * xls[k * 512 + h * 128 + tid];
        o += oh;
    }
    g_res[((size_t)fr * NPTS + n) * 128 + tid] = o * 0.25f;
}
__global__ __launch_bounds__(128) void final_kernel(const float* __restrict__ seq, float* __restrict__ out) {
    const int n = blockIdx.x, c = threadIdx.x, b = n >> 12;
    float w = 0.f;
#pragma unroll
    for (int i = 0; i < 4; i++)
        w += g_attn[b * 4 + i] * g_res[((size_t)i * NPTS + n) * 128 + c];
    const float* last = seq + (size_t)4 * NPTS * 128;
    out[(size_t)n * 256 + c] = last[(size_t)n * 128 + c];
    out[(size_t)n * 256 + 128 + c] = w;
}

// ---------------- launch ----------------
extern "C" void kernel_launch(void* const* d_in, const int* in_sizes, int n_in,
                              void* d_out, int out_size) {
    (void)in_sizes; (void)n_in; (void)out_size;
    const float* seq = (const float*)d_in[0];
    const float* W1  = (const float*)d_in[1];
    const float* b1  = (const float*)d_in[2];
    const float* W2  = (const float*)d_in[3];
    const float* b2  = (const float*)d_in[4];
    const float* Wl  = (const float*)d_in[5];
    const float* Wr  = (const float*)d_in[6];
    const float* aw  = (const float*)d_in[7];
    float* out = (float*)d_out;

    __nv_bfloat16 *pw1h, *pw1l, *pw2h, *pw2l, *pwlh, *pwll, *pwrh, *pwrl;
    cudaGetSymbolAddress((void**)&pw1h, g_w1h); cudaGetSymbolAddress((void**)&pw1l, g_w1l);
    cudaGetSymbolAddress((void**)&pw2h, g_w2h); cudaGetSymbolAddress((void**)&pw2l, g_w2l);
    cudaGetSymbolAddress((void**)&pwlh, g_wlh); cudaGetSymbolAddress((void**)&pwll, g_wll);
    cudaGetSymbolAddress((void**)&pwrh, g_wrh); cudaGetSymbolAddress((void**)&pwrl, g_wrl);

    cudaFuncSetAttribute(mma_gemm_kernel, cudaFuncAttributeMaxDynamicSharedMemorySize, GSMEM);
    cudaFuncSetAttribute(knn_kernel, cudaFuncAttributeMaxDynamicSharedMemorySize, KSMEM);

    zero_gf_kernel<<<80, 256>>>();
    split_seq_kernel<<<10240, 256>>>(seq);
    norm_kernel<<<512, 128>>>(seq);
    tsplit_kernel<<<dim3(4, 4),  dim3(32, 8)>>>(W1, pw1h, pw1l, 128);
    tsplit_kernel<<<dim3(32, 4), dim3(32, 8)>>>(W2, pw2h, pw2l, 1024);
    tsplit_kernel<<<dim3(16, 4), dim3(32, 8)>>>(Wl, pwlh, pwll, 512);
    tsplit_kernel<<<dim3(16, 4), dim3(32, 8)>>>(Wr, pwrh, pwrl, 512);

    mma_gemm_kernel<<<dim3(640, 1),  256, GSMEM>>>(0, b1);   // H1
    mma_gemm_kernel<<<dim3(640, 8),  256, GSMEM>>>(1, b2);   // gf reduce
    attn_kernel<<<1, 512>>>();
    mma_gemm_kernel<<<dim3(128, 20), 256, GSMEM>>>(2, b1);   // XLR
    knn_kernel<<<dim3(32, 4, 4), 256, KSMEM>>>();
    gat_kernel<<<dim3(NPTS, 4), 128>>>(aw);
    final_kernel<<<NPTS, 128>>>(seq, out);
}